// round 16
// baseline (speedup 1.0000x reference)
#include <cuda_runtime.h>

#define NN 100000
#define EE 1600000
#define D 64
#define BN_EPS 1e-5f
#define CAP 64                       // per-node neighbor capacity (Poisson(16) max ~40)
#define MAXOVER 8192                 // overflow side-list capacity
#define RPAD 66                      // padded smem row stride (floats)
#define GROWS 64                     // rows per GEMM block
#define GBLK ((NN + GROWS - 1) / GROWS)   // 1563

// Packed f32x2 FMA (Blackwell): d = a*b + c per 32-bit lane. PTX-only.
#define FMA_F32X2(d, a, b, c) \
    asm("fma.rn.f32x2 %0, %1, %2, %3;" : "=l"(d) : "l"(a), "l"(b), "l"(c))
#define PACK_F32X2(out, lo, hi) \
    asm("mov.b64 %0, {%1, %2};" : "=l"(out) : "f"(lo), "f"(hi))

// Scratch (device globals — no allocation allowed).
__device__ __align__(16) float g_h [NN * D];
__device__ __align__(16) float g_h1[NN * D];
__device__ __align__(16) float g_sum[D];
__device__ __align__(16) float g_sumsq[D];
__device__ __align__(16) int   g_cursor[NN];
__device__ __align__(16) int   g_col[NN * CAP];
__device__ __align__(16) int2  g_over[MAXOVER];
__device__            int      g_overn;

// ---------------------------------------------------------------------------
// 1: zero cursors + BN stat accumulators + overflow counter
// ---------------------------------------------------------------------------
__global__ void k_zero() {
    int i = blockIdx.x * blockDim.x + threadIdx.x;
    if (i < NN) g_cursor[i] = 0;
    if (i < D) { g_sum[i] = 0.f; g_sumsq[i] = 0.f; }
    if (i == D) g_overn = 0;
}

// ---------------------------------------------------------------------------
// 2: direct bucket scatter — no histogram, no scan.
// ---------------------------------------------------------------------------
__global__ void k_fill(const int* __restrict__ ei) {
    int e4 = blockIdx.x * blockDim.x + threadIdx.x;
    if (e4 >= EE / 4) return;
    int4 s = ((const int4*)ei)[e4];
    int4 d = ((const int4*)(ei + EE))[e4];
#pragma unroll
    for (int q = 0; q < 4; q++) {
        int src = (q == 0) ? s.x : (q == 1) ? s.y : (q == 2) ? s.z : s.w;
        int dst = (q == 0) ? d.x : (q == 1) ? d.y : (q == 2) ? d.z : d.w;
        int pos = atomicAdd(&g_cursor[dst], 1);
        if (pos < CAP) {
            g_col[dst * CAP + pos] = src;
        } else {
            int oi = atomicAdd(&g_overn, 1);
            if (oi < MAXOVER) g_over[oi] = make_int2(src, dst);
        }
    }
}

// ---------------------------------------------------------------------------
// 3: gather. One warp per node; lane owns a float2. 8-way edge unroll.
// ---------------------------------------------------------------------------
__global__ void __launch_bounds__(256) k_gather(const float* __restrict__ x,
                                                const float* __restrict__ eps_p) {
    const int w = (blockIdx.x * blockDim.x + threadIdx.x) >> 5;
    const int lane = threadIdx.x & 31;
    if (w >= NN) return;
    const int beg = w * CAP;
    const int end = beg + min(g_cursor[w], CAP);
    const float2* __restrict__ x2 = (const float2*)x;   // row = 32 float2

    float s0x = 0.f, s0y = 0.f, s1x = 0.f, s1y = 0.f;
    float s2x = 0.f, s2y = 0.f, s3x = 0.f, s3y = 0.f;
    int j = beg;
    for (; j + 7 < end; j += 8) {
        int c0 = g_col[j],     c1 = g_col[j + 1];
        int c2 = g_col[j + 2], c3 = g_col[j + 3];
        int c4 = g_col[j + 4], c5 = g_col[j + 5];
        int c6 = g_col[j + 6], c7 = g_col[j + 7];
        float2 v0 = x2[(size_t)c0 * 32 + lane];
        float2 v1 = x2[(size_t)c1 * 32 + lane];
        float2 v2 = x2[(size_t)c2 * 32 + lane];
        float2 v3 = x2[(size_t)c3 * 32 + lane];
        float2 v4 = x2[(size_t)c4 * 32 + lane];
        float2 v5 = x2[(size_t)c5 * 32 + lane];
        float2 v6 = x2[(size_t)c6 * 32 + lane];
        float2 v7 = x2[(size_t)c7 * 32 + lane];
        s0x += v0.x; s0y += v0.y;  s1x += v1.x; s1y += v1.y;
        s2x += v2.x; s2y += v2.y;  s3x += v3.x; s3y += v3.y;
        s0x += v4.x; s0y += v4.y;  s1x += v5.x; s1y += v5.y;
        s2x += v6.x; s2y += v6.y;  s3x += v7.x; s3y += v7.y;
    }
    for (; j < end; j++) {
        int c0 = g_col[j];
        float2 v0 = x2[(size_t)c0 * 32 + lane];
        s0x += v0.x; s0y += v0.y;
    }
    const int novr = g_overn;
    if (novr > 0) {
        const int lim = novr < MAXOVER ? novr : MAXOVER;
        for (int e = 0; e < lim; e++) {
            int2 ed = g_over[e];
            if (ed.y == w) {
                float2 v = x2[(size_t)ed.x * 32 + lane];
                s0x += v.x; s0y += v.y;
            }
        }
    }
    const float sc = 1.f + *eps_p;
    float2 xv = x2[(size_t)w * 32 + lane];
    float2 o;
    o.x = sc * xv.x + ((s0x + s1x) + (s2x + s3x));
    o.y = sc * xv.y + ((s0y + s1y) + (s2y + s3y));
    ((float2*)g_h)[(size_t)w * 32 + lane] = o;
}

// ---------------------------------------------------------------------------
// Shared inner loop: 4 rows x 8 cols per thread (rows rg+16r, cols cg*8..).
// k-loop unrolled 2x with float2 h-loads; only 4 LDS.128 of W per 2 k's.
// ---------------------------------------------------------------------------
__device__ __forceinline__ void gemm_tile_4x8(const float* __restrict__ hb,
                                              const float* __restrict__ Ws,
                                              int cg,
                                              unsigned long long acc[4][4]) {
#pragma unroll 2
    for (int k2 = 0; k2 < D / 2; k2++) {
        const int k = k2 * 2;
        float2 ha  = *(const float2*)&hb[k];
        float2 hbv = *(const float2*)&hb[16 * RPAD + k];
        float2 hc  = *(const float2*)&hb[32 * RPAD + k];
        float2 hd  = *(const float2*)&hb[48 * RPAD + k];
        const ulonglong2* wr0 = (const ulonglong2*)&Ws[k * D + cg * 8];
        const ulonglong2* wr1 = (const ulonglong2*)&Ws[(k + 1) * D + cg * 8];
        ulonglong2 w0a = wr0[0], w0b = wr0[1];
        ulonglong2 w1a = wr1[0], w1b = wr1[1];
        unsigned long long hp0[4], hp1[4];
        PACK_F32X2(hp0[0], ha.x, ha.x);   PACK_F32X2(hp1[0], ha.y, ha.y);
        PACK_F32X2(hp0[1], hbv.x, hbv.x); PACK_F32X2(hp1[1], hbv.y, hbv.y);
        PACK_F32X2(hp0[2], hc.x, hc.x);   PACK_F32X2(hp1[2], hc.y, hc.y);
        PACK_F32X2(hp0[3], hd.x, hd.x);   PACK_F32X2(hp1[3], hd.y, hd.y);
#pragma unroll
        for (int r = 0; r < 4; r++) {
            FMA_F32X2(acc[r][0], hp0[r], w0a.x, acc[r][0]);
            FMA_F32X2(acc[r][1], hp0[r], w0a.y, acc[r][1]);
            FMA_F32X2(acc[r][2], hp0[r], w0b.x, acc[r][2]);
            FMA_F32X2(acc[r][3], hp0[r], w0b.y, acc[r][3]);
        }
#pragma unroll
        for (int r = 0; r < 4; r++) {
            FMA_F32X2(acc[r][0], hp1[r], w1a.x, acc[r][0]);
            FMA_F32X2(acc[r][1], hp1[r], w1a.y, acc[r][1]);
            FMA_F32X2(acc[r][2], hp1[r], w1b.x, acc[r][2]);
            FMA_F32X2(acc[r][3], hp1[r], w1b.y, acc[r][3]);
        }
    }
}

// ---------------------------------------------------------------------------
// 4: h1 = h @ W1 + b1. 64-row blocks, 4x8 tile, 6 blocks/SM.
//    Coalesced staging in/out + fused BN column stats.
// ---------------------------------------------------------------------------
__global__ void __launch_bounds__(128, 6) k_gemm1(const float* __restrict__ W1,
                                                  const float* __restrict__ b1) {
    __shared__ __align__(16) float Ws[D * D];
    __shared__ __align__(16) float bs[D];
    __shared__ __align__(16) float st[GROWS * RPAD];
    const int tid = threadIdx.x;
    const int row0 = blockIdx.x * GROWS;

    for (int i = tid; i < D * D; i += 128) Ws[i] = W1[i];
    if (tid < D) bs[tid] = b1[tid];

    const float2* __restrict__ h2 = (const float2*)g_h;
    for (int idx = tid; idx < GROWS * 32; idx += 128) {
        int r = idx >> 5, c2 = idx & 31;
        int gr = row0 + r;
        float2 v = (gr < NN) ? h2[(size_t)gr * 32 + c2] : make_float2(0.f, 0.f);
        *(float2*)&st[r * RPAD + c2 * 2] = v;
    }
    __syncthreads();

    const int rg = tid & 15;          // rows rg + 16*r
    const int cg = tid >> 4;          // cols [cg*8, cg*8+8)
    const float* hb = &st[rg * RPAD];

    unsigned long long acc[4][4];
    {
        const unsigned long long* bp = (const unsigned long long*)&bs[cg * 8];
#pragma unroll
        for (int j = 0; j < 4; j++) {
            unsigned long long b = bp[j];
            acc[0][j] = b; acc[1][j] = b; acc[2][j] = b; acc[3][j] = b;
        }
    }

    gemm_tile_4x8(hb, Ws, cg, acc);

    __syncthreads();
#pragma unroll
    for (int r = 0; r < 4; r++) {
        int gr = row0 + rg + 16 * r;
        bool v = gr < NN;
        unsigned long long* dst =
            (unsigned long long*)&st[(rg + 16 * r) * RPAD + cg * 8];
#pragma unroll
        for (int j = 0; j < 4; j++) dst[j] = v ? acc[r][j] : 0ull;
    }
    __syncthreads();

    float2* __restrict__ o2 = (float2*)g_h1;
    for (int idx = tid; idx < GROWS * 32; idx += 128) {
        int r = idx >> 5, c2 = idx & 31;
        int gr = row0 + r;
        if (gr < NN)
            o2[(size_t)gr * 32 + c2] = *(const float2*)&st[r * RPAD + c2 * 2];
    }
    if (tid < D) {
        float s = 0.f, q = 0.f;
        for (int i = 0; i < GROWS; i++) {
            float v = st[i * RPAD + tid];
            s += v; q += v * v;
        }
        atomicAdd(&g_sum[tid], s);
        atomicAdd(&g_sumsq[tid], q);
    }
}

// ---------------------------------------------------------------------------
// 5: out = relu(BN(h1)) @ W2 + b2. BN+ReLU during staging, same tiled GEMM.
// ---------------------------------------------------------------------------
__global__ void __launch_bounds__(128, 6) k_gemm2(const float* __restrict__ W2,
                                                  const float* __restrict__ b2,
                                                  const float* __restrict__ gamma,
                                                  const float* __restrict__ beta,
                                                  float* __restrict__ out) {
    __shared__ __align__(16) float Ws[D * D];
    __shared__ __align__(16) float scl[D];
    __shared__ __align__(16) float sft[D];
    __shared__ __align__(16) float bs[D];
    __shared__ __align__(16) float st[GROWS * RPAD];
    const int tid = threadIdx.x;
    const int row0 = blockIdx.x * GROWS;

    for (int i = tid; i < D * D; i += 128) Ws[i] = W2[i];
    if (tid < D) {
        const float inv_n = 1.f / (float)NN;
        float mean = g_sum[tid] * inv_n;
        float var  = g_sumsq[tid] * inv_n - mean * mean;
        float rstd = rsqrtf(var + BN_EPS);
        float s = rstd * gamma[tid];
        scl[tid] = s;
        sft[tid] = beta[tid] - mean * s;
        bs[tid]  = b2[tid];
    }
    __syncthreads();

    const float2* __restrict__ h2 = (const float2*)g_h1;
    for (int idx = tid; idx < GROWS * 32; idx += 128) {
        int r = idx >> 5, c2 = idx & 31;
        int gr = row0 + r;
        float2 v = (gr < NN) ? h2[(size_t)gr * 32 + c2] : make_float2(0.f, 0.f);
        float2 sc2 = *(const float2*)&scl[c2 * 2];
        float2 sf2 = *(const float2*)&sft[c2 * 2];
        v.x = fmaxf(v.x * sc2.x + sf2.x, 0.f);
        v.y = fmaxf(v.y * sc2.y + sf2.y, 0.f);
        *(float2*)&st[r * RPAD + c2 * 2] = v;
    }
    __syncthreads();

    const int rg = tid & 15;
    const int cg = tid >> 4;
    const float* hb = &st[rg * RPAD];

    unsigned long long acc[4][4];
    {
        const unsigned long long* bp = (const unsigned long long*)&bs[cg * 8];
#pragma unroll
        for (int j = 0; j < 4; j++) {
            unsigned long long b = bp[j];
            acc[0][j] = b; acc[1][j] = b; acc[2][j] = b; acc[3][j] = b;
        }
    }

    gemm_tile_4x8(hb, Ws, cg, acc);

    __syncthreads();
#pragma unroll
    for (int r = 0; r < 4; r++) {
        unsigned long long* dst =
            (unsigned long long*)&st[(rg + 16 * r) * RPAD + cg * 8];
#pragma unroll
        for (int j = 0; j < 4; j++) dst[j] = acc[r][j];
    }
    __syncthreads();

    float2* __restrict__ o2 = (float2*)out;
    for (int idx = tid; idx < GROWS * 32; idx += 128) {
        int r = idx >> 5, c2 = idx & 31;
        int gr = row0 + r;
        if (gr < NN)
            o2[(size_t)gr * 32 + c2] = *(const float2*)&st[r * RPAD + c2 * 2];
    }
}

// ---------------------------------------------------------------------------
extern "C" void kernel_launch(void* const* d_in, const int* in_sizes, int n_in,
                              void* d_out, int out_size) {
    const float* x     = (const float*)d_in[0];
    const int*   ei    = (const int*)  d_in[1];   // int32 (JAX demotes int64)
    const float* eps   = (const float*)d_in[2];
    const float* W1    = (const float*)d_in[3];
    const float* b1    = (const float*)d_in[4];
    const float* gamma = (const float*)d_in[5];
    const float* beta  = (const float*)d_in[6];
    const float* W2    = (const float*)d_in[7];
    const float* b2    = (const float*)d_in[8];
    float* out = (float*)d_out;

    k_zero  <<<(NN + 255) / 256, 256>>>();
    k_fill  <<<(EE / 4 + 255) / 256, 256>>>(ei);
    k_gather<<<(NN * 32 + 255) / 256, 256>>>(x, eps);
    k_gemm1 <<<GBLK, 128>>>(W1, b1);
    k_gemm2 <<<GBLK, 128>>>(W2, b2, gamma, beta, out);
}